// round 1
// baseline (speedup 1.0000x reference)
#include <cuda_runtime.h>

// Shapes: x, y : (16, 64, 256, 256) fp32 ; out : (16, 256, 256) fp32
// out[b,i] = sum_c x[b,c,i] * w[b,c],  w[b,c] = sum_j y[b,c,j] / (65536*4194304)

#define NB 16
#define NC 64
#define HW 65536               // 256*256
#define HW4 (HW / 4)           // 16384 float4 per (b,c) plane
#define SCALE (1.0f / (65536.0f * 4194304.0f))  // exact: 2^-38

__device__ float g_w[NB * NC];

// ---------------- Kernel 1: reduce y over hw per (b,c) ----------------
__global__ __launch_bounds__(256) void reduce_y_kernel(const float4* __restrict__ y4) {
    const int plane = blockIdx.x;                // b*64 + c
    const float4* p = y4 + (size_t)plane * HW4;
    const int t = threadIdx.x;

    float s = 0.0f;
    // 16384 float4 / 256 threads = 64 per thread, stride-256 (coalesced)
    #pragma unroll 8
    for (int k = 0; k < 64; ++k) {
        float4 v = __ldcs(&p[t + k * 256]);      // streaming: y read exactly once
        s += (v.x + v.y) + (v.z + v.w);
    }

    // warp reduce
    #pragma unroll
    for (int o = 16; o > 0; o >>= 1)
        s += __shfl_xor_sync(0xFFFFFFFF, s, o);

    __shared__ float smem[8];
    const int lane = t & 31, wid = t >> 5;
    if (lane == 0) smem[wid] = s;
    __syncthreads();
    if (t == 0) {
        float tot = 0.0f;
        #pragma unroll
        for (int i = 0; i < 8; ++i) tot += smem[i];
        g_w[plane] = tot * SCALE;
    }
}

// ---------------- Kernel 2: out[b,i] = sum_c x[b,c,i] * w[b,c] ----------------
__global__ __launch_bounds__(256) void weighted_sum_kernel(const float4* __restrict__ x4,
                                                           float4* __restrict__ out4) {
    // 262144 float4 outputs total; 1024 blocks * 256 threads.
    // 16384 float4 per batch; 256 | 16384, so each block sits in one batch.
    const int idx = blockIdx.x * 256 + threadIdx.x;
    const int b = idx >> 14;                     // / 16384
    const int i4 = idx & (HW4 - 1);              // % 16384

    __shared__ float w[NC];
    if (threadIdx.x < NC) w[threadIdx.x] = g_w[b * NC + threadIdx.x];
    __syncthreads();

    const float4* px = x4 + ((size_t)b * NC) * HW4 + i4;

    float4 acc = make_float4(0.f, 0.f, 0.f, 0.f);
    #pragma unroll 8
    for (int c = 0; c < NC; ++c) {
        float4 v = __ldcs(&px[(size_t)c * HW4]); // streaming: x read exactly once
        float wc = w[c];
        acc.x += v.x * wc;
        acc.y += v.y * wc;
        acc.z += v.z * wc;
        acc.w += v.w * wc;
    }
    out4[idx] = acc;
}

extern "C" void kernel_launch(void* const* d_in, const int* in_sizes, int n_in,
                              void* d_out, int out_size) {
    const float4* x4 = (const float4*)d_in[0];
    const float4* y4 = (const float4*)d_in[1];
    float4* out4 = (float4*)d_out;

    reduce_y_kernel<<<NB * NC, 256>>>(y4);
    weighted_sum_kernel<<<(NB * HW4) / 256, 256>>>(x4, out4);
}